// round 17
// baseline (speedup 1.0000x reference)
#include <cuda_runtime.h>
#include <cuda_fp16.h>
#include <cstdint>

#define BB   2
#define CFI  32
#define HH   192
#define WWD  192
#define NN   (HH*WWD)        // 36864
#define NUMK 16
#define CT   67
#define EPSL 1e-5f
#define NT   (NN/256)        // 144 (pq tiles)
#define NB2  (NN/8)          // 4608 main tiles: 8 samples x 16 k per block

// ---------------- scratch (static device globals; no allocation) ----------------
// g_P/g_Q rows are PERMUTED: within a row, channel c sits at
// p = ((c>>1)&3)*8 + ((c>>3)<<1) + (c&1)  (thread tg owns floats [tg*8, tg*8+8))
__device__ float g_P[BB*NN*CFI];
__device__ float g_Q[BB*NN*CFI];

// stage-1 constants, vectorized: [(q*4+tg)] -> 8 floats {w1p.xy, w1a.xy, w1b.xy, t1.xy}
__device__ float g_C1[16*8];
// layer weights, vectorized: uint4[(nt*4+tg)*8+g] = {ks0b0, ks0b1, ks1b0, ks1b1}
__device__ uint4 g_W2p4[128];
__device__ uint4 g_W3p4[128];
__device__ uint4 g_W4p4[128];
// head weights: uint4[tg*8+g] = {ks0b0, ks0b1, ks1b0, ks1b1}
__device__ uint4 g_Wcp4[32];
// biases rearranged: [tg*8 + nt*2 + e] = t[8*nt + 2*tg + e]
__device__ float g_t2r[32], g_t3r[32], g_t4r[32];
__device__ float g_bcv[3];
__device__ int   g_args64;

__device__ __forceinline__ float frcp(float x) { float y; asm("rcp.approx.f32 %0, %1;" : "=f"(y) : "f"(x)); return y; }
__device__ __forceinline__ float fex2(float x) { float y; asm("ex2.approx.f32 %0, %1;" : "=f"(y) : "f"(x)); return y; }

// ---------------- packed f32x2 helpers ----------------
__device__ __forceinline__ float2 fma2(float2 a, float2 b, float2 c) {
    float2 r;
    asm("fma.rn.f32x2 %0, %1, %2, %3;"
        : "=l"(*(unsigned long long*)&r)
        : "l"(*(const unsigned long long*)&a),
          "l"(*(const unsigned long long*)&b),
          "l"(*(const unsigned long long*)&c));
    return r;
}
__device__ __forceinline__ float2 mul2(float2 a, float2 b) {
    float2 r;
    asm("mul.rn.f32x2 %0, %1, %2;"
        : "=l"(*(unsigned long long*)&r)
        : "l"(*(const unsigned long long*)&a),
          "l"(*(const unsigned long long*)&b));
    return r;
}
__device__ __forceinline__ float2 add2(float2 a, float2 b) {
    float2 r;
    asm("add.rn.f32x2 %0, %1, %2;"
        : "=l"(*(unsigned long long*)&r)
        : "l"(*(const unsigned long long*)&a),
          "l"(*(const unsigned long long*)&b));
    return r;
}
__device__ __forceinline__ float2 d2(float v) { return make_float2(v, v); }

// packed fast gelu: 0.5*(x + |x|*erf(|x|/sqrt2)), erf via A&S 7.1.25 3-term
__device__ __forceinline__ float2 gelu2(float2 x) {
    unsigned long long ux = (*(unsigned long long*)&x) & 0x7FFFFFFF7FFFFFFFULL;
    float2 ax = *(float2*)&ux;
    float2 z  = mul2(ax, d2(0.70710678118654752f));
    float2 q  = fma2(z, d2(0.47047f), d2(1.0f));
    float2 t; t.x = frcp(q.x); t.y = frcp(q.y);
    float2 s  = mul2(mul2(z, z), d2(-1.4426950408889634f));
    float2 e; e.x = fex2(s.x); e.y = fex2(s.y);
    float2 h  = fma2(d2(0.7478556f), t, d2(-0.0958798f));
    h = fma2(h, t, d2(0.3480242f));
    h = mul2(h, t);
    float2 he = mul2(h, e);
    float2 E  = fma2(he, d2(-1.0f), d2(1.0f));
    float2 g  = mul2(ax, E);
    return mul2(add2(x, g), d2(0.5f));
}

// m16n8k16 fp16 MMA, row.col, fp32 accumulate in-place
__device__ __forceinline__ void mma16(float* d, unsigned a0, unsigned a1, unsigned a2, unsigned a3,
                                      unsigned b0, unsigned b1) {
    asm volatile(
        "mma.sync.aligned.m16n8k16.row.col.f32.f16.f16.f32 "
        "{%0,%1,%2,%3}, {%4,%5,%6,%7}, {%8,%9}, {%0,%1,%2,%3};"
        : "+f"(d[0]), "+f"(d[1]), "+f"(d[2]), "+f"(d[3])
        : "r"(a0), "r"(a1), "r"(a2), "r"(a3), "r"(b0), "r"(b1));
}

// channel -> permuted position within a 32-float P/Q row
__device__ __forceinline__ int permc(int c) {
    return ((c >> 1) & 3) * 8 + ((c >> 3) << 1) + (c & 1);
}

__device__ __forceinline__ unsigned packw(const float* W, const float* inv, int n, int k2) {
    __half2 p = __floats2half2_rn(W[n*32 + 2*k2]*inv[n], W[n*32 + 2*k2 + 1]*inv[n]);
    return *(unsigned*)&p;
}

// ---------------- kernel 1: P/Q GEMM (blocks 0..BB*NT-1) + fused prep (last block) --------
__global__ void pq_kernel(
    const float* __restrict__ If,
    const float* __restrict__ W1, const float* __restrict__ g1, const float* __restrict__ b1,
    const float* __restrict__ m1, const float* __restrict__ v1,
    const float* __restrict__ W2, const float* __restrict__ g2, const float* __restrict__ b2,
    const float* __restrict__ m2, const float* __restrict__ v2,
    const float* __restrict__ W3, const float* __restrict__ g3, const float* __restrict__ b3,
    const float* __restrict__ m3, const float* __restrict__ v3,
    const float* __restrict__ W4, const float* __restrict__ g4, const float* __restrict__ b4,
    const float* __restrict__ m4, const float* __restrict__ v4,
    const float* __restrict__ Wc, const float* __restrict__ bc,
    const int*   __restrict__ args_i32)
{
    int tid = threadIdx.x;

    // ---- last block: main-side prep (vectorized-layout packing) ----
    if (blockIdx.x == BB*NT) {
        __shared__ float inv1[32], inv2[32], inv3[32], inv4[32];
        __shared__ float t2s[32], t3s[32], t4s[32];
        __shared__ int flag;
        if (tid == 0) flag = 0;
        if (tid < 32) {
            float i1 = g1[tid]*rsqrtf(v1[tid]+EPSL); inv1[tid]=i1;
            float i2 = g2[tid]*rsqrtf(v2[tid]+EPSL); inv2[tid]=i2; t2s[tid]=b2[tid]-m2[tid]*i2;
            float i3 = g3[tid]*rsqrtf(v3[tid]+EPSL); inv3[tid]=i3; t3s[tid]=b3[tid]-m3[tid]*i3;
            float i4 = g4[tid]*rsqrtf(v4[tid]+EPSL); inv4[tid]=i4; t4s[tid]=b4[tid]-m4[tid]*i4;
        }
        if (tid < 3) g_bcv[tid] = bc[tid];
        __syncthreads();
        // parallel args-dtype detect: int64 little-endian => odd words all zero
        if (tid < 128) {
            if (args_i32[2*tid+1] != 0) flag = 1;
        }
        // layer weights, vectorized layout: idx < 128 -> (nt,tg,g)
        if (tid < 128) {
            int g = tid & 7, tg = (tid >> 3) & 3, nt = tid >> 5;
            int n = 8*nt + g;
            int slot = (nt*4 + tg)*8 + g;
            g_W2p4[slot] = make_uint4(packw(W2, inv2, n, tg),     packw(W2, inv2, n, tg+4),
                                      packw(W2, inv2, n, 8+tg),   packw(W2, inv2, n, 8+tg+4));
            g_W3p4[slot] = make_uint4(packw(W3, inv3, n, tg),     packw(W3, inv3, n, tg+4),
                                      packw(W3, inv3, n, 8+tg),   packw(W3, inv3, n, 8+tg+4));
            g_W4p4[slot] = make_uint4(packw(W4, inv4, n, tg),     packw(W4, inv4, n, 8+tg) /*placeholder*/,
                                      0, 0);
            // fix: proper order {ks0b0, ks0b1, ks1b0, ks1b1}
            g_W4p4[slot] = make_uint4(packw(W4, inv4, n, tg),     packw(W4, inv4, n, tg+4),
                                      packw(W4, inv4, n, 8+tg),   packw(W4, inv4, n, 8+tg+4));
        }
        // stage-1 constants: 16 slots (q,tg) x 8 floats
        if (tid < 16) {
            int q = tid >> 2, tg = tid & 3;
            int c0 = 8*q + 2*tg;
            float i1a = inv1[c0], i1b = inv1[c0+1];
            float* dst = g_C1 + tid*8;
            dst[0] = W1[c0*CT+64]*i1a;     dst[1] = W1[(c0+1)*CT+64]*i1b;
            dst[2] = W1[c0*CT+65]*i1a;     dst[3] = W1[(c0+1)*CT+65]*i1b;
            dst[4] = W1[c0*CT+66]*i1a;     dst[5] = W1[(c0+1)*CT+66]*i1b;
            dst[6] = b1[c0]-m1[c0]*i1a;    dst[7] = b1[c0+1]-m1[c0+1]*i1b;
        }
        // biases rearranged: [tg*8 + nt*2 + e] = t[8*nt + 2*tg + e]
        if (tid < 32) {
            int tg = tid >> 3, nt = (tid >> 1) & 3, e = tid & 1;
            int ch = 8*nt + 2*tg + e;
            g_t2r[tid] = t2s[ch];
            g_t3r[tid] = t3s[ch];
            g_t4r[tid] = t4s[ch];
        }
        // head weights: uint4[tg*8+g]
        if (tid < 32) {
            int tg = tid >> 3, g = tid & 7;
            // word(k2, n=g): n<3 ? Wc row n : 0
            auto hw = [&](int k2) -> unsigned {
                float w0 = (g < 3) ? Wc[g*32 + 2*k2]     : 0.f;
                float w1 = (g < 3) ? Wc[g*32 + 2*k2 + 1] : 0.f;
                __half2 p = __floats2half2_rn(w0, w1);
                return *(unsigned*)&p;
            };
            g_Wcp4[tid] = make_uint4(hw(tg), hw(tg+4), hw(8+tg), hw(8+tg+4));
        }
        __syncthreads();
        if (tid == 0) g_args64 = (flag == 0);
        return;
    }

    // ---- P/Q GEMM blocks: fold W1 locally, compute, store permuted ----
    __shared__ float inv1s[32];
    __shared__ float wf[2048];
    __shared__ float tb[256*33];

    int b    = blockIdx.x / NT;
    int tile = blockIdx.x % NT;
    int n0   = tile * 256;

    if (tid < 32) inv1s[tid] = g1[tid]*rsqrtf(v1[tid]+EPSL);
    __syncthreads();
    for (int idx = tid; idx < 2048; idx += 256) {
        int r = idx >> 5, i = idx & 31;
        wf[idx] = (r < 32) ? W1[r*CT + i] * inv1s[r]
                           : W1[(r-32)*CT + 32 + i] * inv1s[r-32];
    }

    int n = n0 + tid;
    float x[32];
    #pragma unroll
    for (int i = 0; i < 32; i++) x[i] = If[((size_t)b*32 + i)*NN + n];
    __syncthreads();

    size_t base = ((size_t)b*NN + n0) * 32;

    #pragma unroll
    for (int c = 0; c < 32; c++) {
        float acc = 0.f;
        #pragma unroll
        for (int i = 0; i < 32; i += 4) {
            float4 w = *(const float4*)&wf[c*32 + i];
            acc += w.x*x[i] + w.y*x[i+1] + w.z*x[i+2] + w.w*x[i+3];
        }
        tb[tid*33 + c] = acc;
    }
    __syncthreads();
    for (int idx = tid; idx < 8192; idx += 256)
        g_P[base + (idx & ~31) + permc(idx & 31)] = tb[(idx >> 5)*33 + (idx & 31)];
    __syncthreads();

    #pragma unroll
    for (int c = 0; c < 32; c++) {
        float acc = 0.f;
        #pragma unroll
        for (int i = 0; i < 32; i += 4) {
            float4 w = *(const float4*)&wf[(32+c)*32 + i];
            acc += w.x*x[i] + w.y*x[i+1] + w.z*x[i+2] + w.w*x[i+3];
        }
        tb[tid*33 + c] = acc;
    }
    __syncthreads();
    for (int idx = tid; idx < 8192; idx += 256)
        g_Q[base + (idx & ~31) + permc(idx & 31)] = tb[(idx >> 5)*33 + (idx & 31)];
}

// ---------------- register-resident MLP layer (single m16 tile per warp) ----------------
// x layout: x[nt*4 + 2*hh + par], channel = 8*nt + 2*tg + par, row = g + 8*hh
template<bool ADD>
__device__ __forceinline__ void layer_reg(
    const float* xin, float* xout,
    const uint4* __restrict__ wp4, const float* __restrict__ biasr,
    const float* resid, int g, int tg)
{
    unsigned ah[8];
    #pragma unroll
    for (int nt = 0; nt < 4; nt++) {
        #pragma unroll
        for (int hh = 0; hh < 2; hh++) {
            __half2 p = __floats2half2_rn(xin[nt*4 + 2*hh], xin[nt*4 + 2*hh + 1]);
            ah[nt*2 + hh] = *(unsigned*)&p;
        }
    }
    float d[16];
    {
        float4 bv0 = __ldg((const float4*)(biasr + tg*8));
        float4 bv1 = __ldg((const float4*)(biasr + tg*8 + 4));
        d[0]=bv0.x; d[1]=bv0.y; d[2]=bv0.x; d[3]=bv0.y;
        d[4]=bv0.z; d[5]=bv0.w; d[6]=bv0.z; d[7]=bv0.w;
        d[8]=bv1.x; d[9]=bv1.y; d[10]=bv1.x; d[11]=bv1.y;
        d[12]=bv1.z; d[13]=bv1.w; d[14]=bv1.z; d[15]=bv1.w;
    }
    #pragma unroll
    for (int nt = 0; nt < 4; nt++) {
        uint4 wv = __ldg(wp4 + (nt*4 + tg)*8 + g);
        mma16(d + nt*4, ah[0], ah[1], ah[2], ah[3], wv.x, wv.y);   // ks=0
        mma16(d + nt*4, ah[4], ah[5], ah[6], ah[7], wv.z, wv.w);   // ks=1
    }
    #pragma unroll
    for (int i = 0; i < 16; i += 2) {
        float2 v = make_float2(d[i], d[i+1]);
        if (ADD) v = add2(v, make_float2(resid[i], resid[i+1]));
        float2 r = gelu2(v);
        xout[i] = r.x; xout[i+1] = r.y;
    }
}

// NOTE on ah ordering: ah[nt*2+hh] holds k-group nt (channels 8nt+2tg..), row g+8hh.
// For the mma A-fragment of ks: a0,a1 = k-groups 2ks (rows g, g+8), a2,a3 = k-group 2ks+1.
// ah[0..3] = {nt0/hh0, nt0/hh1, nt1/hh0, nt1/hh1} == ks=0 fragment; ah[4..7] == ks=1. OK.

// ---------------- kernel 2: fused MLP + mma head + softmax epilogue ----------------
// block: 8 samples x 16 k. warp w: rows 0-7 = k=2w, rows 8-15 = k=2w+1, sample n0+g.
__global__ void __launch_bounds__(256) main_kernel(
    const float* __restrict__ Pf,
    const float* __restrict__ Of,
    const void*  __restrict__ args,
    float* __restrict__ out)
{
    __shared__ float sU[NUMK][8];
    __shared__ float sOm[NUMK][8];

    int b  = blockIdx.x / NB2;
    int n0 = (blockIdx.x % NB2) * 8;
    int tid = threadIdx.x;
    int w = tid >> 5, lane = tid & 31;
    int g = lane >> 2, tg = lane & 3;

    float xa[16], xb[16];
    float pfs[2];
    int n = n0 + g;

    // stage 1: h1 in D-frag register layout; hh selects k = 2w+hh
    {
        float2 w1p2[4], w1a2[4], w1b2[4], t12[4];
        #pragma unroll
        for (int q = 0; q < 4; q++) {
            float4 cA = __ldg((const float4*)g_C1 + (q*4 + tg)*2);
            float4 cB = __ldg((const float4*)g_C1 + (q*4 + tg)*2 + 1);
            w1p2[q] = make_float2(cA.x, cA.y);
            w1a2[q] = make_float2(cA.z, cA.w);
            w1b2[q] = make_float2(cB.x, cB.y);
            t12[q]  = make_float2(cB.z, cB.w);
        }
        int use64 = g_args64;
        const float4* P4 = (const float4*)(g_P + ((size_t)(b*NN + n))*32 + tg*8);
        float4 pA = __ldg(P4), pB = __ldg(P4 + 1);
        float2 pq[4];
        pq[0] = make_float2(pA.x, pA.y); pq[1] = make_float2(pA.z, pA.w);
        pq[2] = make_float2(pB.x, pB.y); pq[3] = make_float2(pB.z, pB.w);
        #pragma unroll
        for (int hh = 0; hh < 2; hh++) {
            int k = 2*w + hh;
            size_t ai = ((size_t)(b*NUMK + k))*NN + n;
            int j;
            if (use64) j = (int)__ldg((const long long*)args + ai);
            else       j = __ldg((const int*)args + ai);
            float pf = __ldg(Pf + (size_t)b*NN + j);
            pfs[hh] = pf;
            float2 pf2 = d2(pf);
            float2 o02 = d2(__ldg(Of + ((size_t)(b*2+0)*NUMK + k)*NN + n));
            float2 o12 = d2(__ldg(Of + ((size_t)(b*2+1)*NUMK + k)*NN + n));
            const float4* Q4 = (const float4*)(g_Q + ((size_t)(b*NN + j))*32 + tg*8);
            float4 qA = __ldg(Q4), qB = __ldg(Q4 + 1);
            float2 qq[4];
            qq[0] = make_float2(qA.x, qA.y); qq[1] = make_float2(qA.z, qA.w);
            qq[2] = make_float2(qB.x, qB.y); qq[3] = make_float2(qB.z, qB.w);
            #pragma unroll
            for (int q = 0; q < 4; q++) {
                float2 z = add2(add2(pq[q], qq[q]), t12[q]);
                z = fma2(w1p2[q], pf2, z);
                z = fma2(w1a2[q], o02, z);
                z = fma2(w1b2[q], o12, z);
                float2 r = gelu2(z);
                xa[q*4 + 2*hh]     = r.x;
                xa[q*4 + 2*hh + 1] = r.y;
            }
        }
    }

    layer_reg<false>(xa, xb, g_W2p4, g_t2r, nullptr, g, tg);   // h2 = xb
    layer_reg<false>(xb, xa, g_W3p4, g_t3r, nullptr, g, tg);   // l3 = xa
    layer_reg<true >(xa, xa, g_W4p4, g_t4r, xb,      g, tg);   // XF = gelu(h2 + bn4(W4 l3))

    // head as one fp16 mma pair: D cols 0=A, 1=B, 2=Om; rows = instances
    {
        unsigned ah[8];
        #pragma unroll
        for (int nt = 0; nt < 4; nt++) {
            #pragma unroll
            for (int hh = 0; hh < 2; hh++) {
                __half2 p = __floats2half2_rn(xa[nt*4 + 2*hh], xa[nt*4 + 2*hh + 1]);
                ah[nt*2 + hh] = *(unsigned*)&p;
            }
        }
        float dh[4] = {0.f, 0.f, 0.f, 0.f};
        uint4 wv = __ldg(g_Wcp4 + tg*8 + g);
        mma16(dh, ah[0], ah[1], ah[2], ah[3], wv.x, wv.y);
        mma16(dh, ah[4], ah[5], ah[6], ah[7], wv.z, wv.w);
        float bc0 = g_bcv[0], bc1 = g_bcv[1], bc2 = g_bcv[2];
        if (tg == 0) {
            #pragma unroll
            for (int hh = 0; hh < 2; hh++) {
                int k = 2*w + hh;
                sU[k][g] = (dh[2*hh] + bc0 + 1.0f)*pfs[hh] + (dh[2*hh+1] + bc1);
            }
        }
        if (tg == 1) {
            #pragma unroll
            for (int hh = 0; hh < 2; hh++) {
                int k = 2*w + hh;
                sOm[k][g] = dh[2*hh] + bc2;
            }
        }
    }
    __syncthreads();

    // softmax over k + weighted sum; threads 0-7 each own one sample
    if (tid < 8) {
        float om[NUMK];
        float m = -3.4e38f;
        #pragma unroll
        for (int k = 0; k < NUMK; k++) {
            om[k] = sOm[k][tid];
            m = fmaxf(m, om[k]);
        }
        float num = 0.f, den = 0.f;
        #pragma unroll
        for (int k = 0; k < NUMK; k++) {
            float e = fex2((om[k] - m) * 1.4426950408889634f);
            den += e;
            num += e * sU[k][tid];
        }
        out[(size_t)b*NN + n0 + tid] = num * frcp(den);
    }
}

// ---------------- launch ----------------
extern "C" void kernel_launch(void* const* d_in, const int* in_sizes, int n_in,
                              void* d_out, int out_size)
{
    const float* If = (const float*)d_in[0];
    const float* Pf = (const float*)d_in[1];
    const float* Of = (const float*)d_in[2];
    const void*  args = d_in[3];
    const float* W1 = (const float*)d_in[4];
    const float* g1 = (const float*)d_in[5];
    const float* b1 = (const float*)d_in[6];
    const float* m1 = (const float*)d_in[7];
    const float* v1 = (const float*)d_in[8];
    const float* W2 = (const float*)d_in[9];
    const float* g2 = (const float*)d_in[10];
    const float* b2 = (const float*)d_in[11];
    const float* m2 = (const float*)d_in[12];
    const float* v2 = (const float*)d_in[13];
    const float* W3 = (const float*)d_in[14];
    const float* g3 = (const float*)d_in[15];
    const float* b3 = (const float*)d_in[16];
    const float* m3 = (const float*)d_in[17];
    const float* v3 = (const float*)d_in[18];
    const float* W4 = (const float*)d_in[19];
    const float* g4 = (const float*)d_in[20];
    const float* b4 = (const float*)d_in[21];
    const float* m4 = (const float*)d_in[22];
    const float* v4 = (const float*)d_in[23];
    const float* Wc = (const float*)d_in[24];
    const float* bc = (const float*)d_in[25];

    pq_kernel<<<BB*NT + 1, 256>>>(If,
                                  W1, g1, b1, m1, v1,
                                  W2, g2, b2, m2, v2,
                                  W3, g3, b3, m3, v3,
                                  W4, g4, b4, m4, v4,
                                  Wc, bc, (const int*)args);

    main_kernel<<<BB*NB2, 256>>>(Pf, Of, args, (float*)d_out);
}